// round 14
// baseline (speedup 1.0000x reference)
#include <cuda_runtime.h>
#include <cuda_bf16.h>
#include <cstdint>

// ---------------- problem dims ----------------
#define DIN   4096
#define DOUT  4096
#define NROWS 16384            // 8 * 2048

// Feature probe: tcgen05-capable pass defines __CUDA_ARCH_FEAT_SM103_ALL.
#if defined(__CUDA_ARCH__) && defined(__CUDA_ARCH_FEAT_SM103_ALL)
#define TC_ACTIVE 1
#else
#define TC_ACTIVE 0
#endif

// ---------------- scratch (device globals: no allocation allowed) ----------------
__device__ __nv_bfloat16 g_xhi[(size_t)NROWS * DIN];   // 128MB
__device__ __nv_bfloat16 g_xlo[(size_t)NROWS * DIN];   // 128MB
__device__ __nv_bfloat16 g_whi[(size_t)DOUT * DIN];    // 32MB
__device__ __nv_bfloat16 g_wlo[(size_t)DOUT * DIN];    // 32MB
__device__ unsigned int  g_probe[4096];                // arch-probe sink (never read)

// ---------------- common helpers ----------------
__device__ __forceinline__ uint32_t smem_to_u32(const void* smem_ptr) {
    uint32_t addr;
    asm("{ .reg .u64 tmp; cvta.to.shared.u64 tmp, %1; cvt.u32.u64 %0, tmp; }"
        : "=r"(addr) : "l"(smem_ptr));
    return addr;
}

__device__ __forceinline__ uint32_t swz(uint32_t off) {   // SW128 swizzle
    return off ^ ((off >> 3) & 0x70);
}

__device__ __forceinline__ uint32_t pack2bf(__nv_bfloat16 a, __nv_bfloat16 b) {
    return (uint32_t)__bfloat16_as_ushort(a) | ((uint32_t)__bfloat16_as_ushort(b) << 16);
}

// ================= arch probe: body only under sm_103a feature pass =================
__global__ void probe_sm103a_feat_kernel() {
#if TC_ACTIVE
    unsigned i = blockIdx.x * blockDim.x + threadIdx.x;
    if (i < 4096) g_probe[i] = i * 2654435761u;
#endif
}

// ================= prep kernels =================
__global__ void split_x_kernel(const float4* __restrict__ x) {
    size_t i = (size_t)blockIdx.x * blockDim.x + threadIdx.x;
    if (i >= (size_t)NROWS * DIN / 4) return;
    float4 v = x[i];
    __nv_bfloat16 h0 = __float2bfloat16(v.x);
    __nv_bfloat16 h1 = __float2bfloat16(v.y);
    __nv_bfloat16 h2 = __float2bfloat16(v.z);
    __nv_bfloat16 h3 = __float2bfloat16(v.w);
    __nv_bfloat16 l0 = __float2bfloat16(v.x - __bfloat162float(h0));
    __nv_bfloat16 l1 = __float2bfloat16(v.y - __bfloat162float(h1));
    __nv_bfloat16 l2 = __float2bfloat16(v.z - __bfloat162float(h2));
    __nv_bfloat16 l3 = __float2bfloat16(v.w - __bfloat162float(h3));
    ((uint2*)g_xhi)[i] = make_uint2(pack2bf(h0, h1), pack2bf(h2, h3));
    ((uint2*)g_xlo)[i] = make_uint2(pack2bf(l0, l1), pack2bf(l2, l3));
}

__device__ __forceinline__ float gumbel_of(float u) {
    return -logf(-logf(u + 1e-10f) + 1e-10f);
}

__global__ void mask_split_w_kernel(const float* __restrict__ weight,
                                    const float* __restrict__ scores,
                                    const float* __restrict__ noise) {
    size_t gi = (size_t)blockIdx.x * blockDim.x + threadIdx.x;
    if (gi >= (size_t)DOUT * (DIN / 4)) return;
    float4 s4 = ((const float4*)scores)[gi];
    float4 u4 = ((const float4*)noise)[gi];
    float y[4];
    y[0] = s4.x + gumbel_of(u4.x);
    y[1] = s4.y + gumbel_of(u4.y);
    y[2] = s4.z + gumbel_of(u4.z);
    y[3] = s4.w + gumbel_of(u4.w);
    float mx = fmaxf(fmaxf(y[0], y[1]), fmaxf(y[2], y[3]));
    float e[4];
#pragma unroll
    for (int j = 0; j < 4; ++j) e[j] = expf(y[j] - mx);
    float ssum = ((e[0] + e[1]) + e[2]) + e[3];
    float q[4];
#pragma unroll
    for (int j = 0; j < 4; ++j) q[j] = e[j] / ssum;
    // top-2 (stable: ties -> lower index, matching jax top_k)
    int i0 = 0;
#pragma unroll
    for (int j = 1; j < 4; ++j) if (q[j] > q[i0]) i0 = j;
    int i1 = (i0 == 0) ? 1 : 0;
#pragma unroll
    for (int j = 0; j < 4; ++j) if (j != i0 && q[j] > q[i1]) i1 = j;

    float4 w4 = ((const float4*)weight)[gi];
    float wm[4] = {w4.x, w4.y, w4.z, w4.w};
#pragma unroll
    for (int j = 0; j < 4; ++j) if (j != i0 && j != i1) wm[j] = 0.0f;

    __nv_bfloat16 h[4], l[4];
#pragma unroll
    for (int j = 0; j < 4; ++j) {
        h[j] = __float2bfloat16(wm[j]);
        l[j] = __float2bfloat16(wm[j] - __bfloat162float(h[j]));
    }
    ((uint2*)g_whi)[gi] = make_uint2(pack2bf(h[0], h[1]), pack2bf(h[2], h[3]));
    ((uint2*)g_wlo)[gi] = make_uint2(pack2bf(l[0], l[1]), pack2bf(l[2], l[3]));
}

// =====================================================================
// GEMM: mma.sync.m16n8k16 bf16, 128x128 CTA tile, cp.async double buffer.
// D[m,n] = sum_k A[m,k]*B[n,k], 3-term bf16 hi/lo split, fp32 accum.
// =====================================================================
#define FTM 128
#define FTN 128
#define FKS 64                  // K elems per stage (128B rows, SW128)
#define FNST (DIN / FKS)        // 64
#define F_TILE 16384            // one 128x64 bf16 tile (16KB), swizzled
#define F_STAGE (4 * F_TILE)    // Ahi,Alo,Bhi,Blo = 64KB
#define F_SMEM (2 * F_STAGE)    // 131072

__device__ __forceinline__ void ldmx4(uint32_t* r, uint32_t addr) {
    asm volatile("ldmatrix.sync.aligned.m8n8.x4.shared.b16 {%0,%1,%2,%3}, [%4];"
        : "=r"(r[0]), "=r"(r[1]), "=r"(r[2]), "=r"(r[3]) : "r"(addr));
}

__device__ __forceinline__ void mma16816(float* c, const uint32_t* a, uint32_t b0, uint32_t b1) {
    asm volatile(
        "mma.sync.aligned.m16n8k16.row.col.f32.bf16.bf16.f32 "
        "{%0,%1,%2,%3}, {%4,%5,%6,%7}, {%8,%9}, {%0,%1,%2,%3};"
        : "+f"(c[0]), "+f"(c[1]), "+f"(c[2]), "+f"(c[3])
        : "r"(a[0]), "r"(a[1]), "r"(a[2]), "r"(a[3]), "r"(b0), "r"(b1));
}

__device__ __forceinline__ void cp16(uint32_t dst, const void* src) {
    asm volatile("cp.async.cg.shared.global [%0], [%1], 16;" :: "r"(dst), "l"(src));
}
#define CP_COMMIT() asm volatile("cp.async.commit_group;" ::: "memory")
#define CP_WAIT0()  asm volatile("cp.async.wait_group 0;" ::: "memory")

// issue one full stage: 4 tiles x 1024 chunks of 16B; 256 threads x 4 chunks/tile
__device__ __forceinline__ void issue_stage(uint32_t sbase, int tid, int m0, int n0, int k0) {
#pragma unroll
    for (int i = 0; i < 4; ++i) {
        int ch = tid + i * 256;               // 0..1023
        int row = ch >> 3, col = ch & 7;      // row 0..127, col 0..7 (16B chunks)
        uint32_t sw = swz((uint32_t)((row << 7) + (col << 4)));
        size_t ax = (size_t)(m0 + row) * DIN + k0 + (col << 3);
        size_t bx = (size_t)(n0 + row) * DIN + k0 + (col << 3);
        cp16(sbase + 0 * F_TILE + sw, g_xhi + ax);
        cp16(sbase + 1 * F_TILE + sw, g_xlo + ax);
        cp16(sbase + 2 * F_TILE + sw, g_whi + bx);
        cp16(sbase + 3 * F_TILE + sw, g_wlo + bx);
    }
}

__global__ __launch_bounds__(256, 1)
void gemm_mma_kernel(const float* __restrict__ bias, float* __restrict__ out) {
    extern __shared__ __align__(128) char fsmem[];
    const uint32_t smem_u = smem_to_u32(fsmem);
    const int tid = threadIdx.x;
    const int wid = tid >> 5;
    const int lane = tid & 31;
    const int wm = wid >> 2;          // 0..1 -> 64-row slab (M)
    const int wn = wid & 3;           // 0..3 -> 32-col slab (N)
    const int m0 = blockIdx.x * FTM;
    const int n0 = blockIdx.y * FTN;

    issue_stage(smem_u, tid, m0, n0, 0);
    CP_COMMIT();

    float acc[4][4][4];
#pragma unroll
    for (int a = 0; a < 4; ++a)
#pragma unroll
        for (int b = 0; b < 4; ++b)
#pragma unroll
            for (int c = 0; c < 4; ++c) acc[a][b][c] = 0.0f;

    const uint32_t a_row = (uint32_t)(wm * 64 + (lane & 15));
    const uint32_t b_row = (uint32_t)(wn * 32 + (lane & 15));
    const uint32_t kqual = ((uint32_t)(lane >> 4)) << 4;   // byte offset of k-half

    for (int k = 0; k < FNST; ++k) {
        CP_WAIT0();
        __syncthreads();
        if (k + 1 < FNST) {
            issue_stage(smem_u + (uint32_t)(((k + 1) & 1) * F_STAGE), tid, m0, n0, (k + 1) * FKS);
            CP_COMMIT();
        }
        const uint32_t cur = smem_u + (uint32_t)((k & 1) * F_STAGE);
#pragma unroll
        for (int ks = 0; ks < 4; ++ks) {
            uint32_t ah[4][4], al[4][4], bh[2][4], bl[2][4];
#pragma unroll
            for (int mi = 0; mi < 4; ++mi) {
                uint32_t sa = swz(((a_row + mi * 16) << 7) + (ks << 5) + kqual);
                ldmx4(ah[mi], cur + 0 * F_TILE + sa);
                ldmx4(al[mi], cur + 1 * F_TILE + sa);
            }
#pragma unroll
            for (int nj = 0; nj < 2; ++nj) {
                uint32_t sb = swz(((b_row + nj * 16) << 7) + (ks << 5) + kqual);
                ldmx4(bh[nj], cur + 2 * F_TILE + sb);
                ldmx4(bl[nj], cur + 3 * F_TILE + sb);
            }
#pragma unroll
            for (int mi = 0; mi < 4; ++mi) {
#pragma unroll
                for (int ni = 0; ni < 4; ++ni) {
                    const int j = ni >> 1, s = ni & 1;
                    mma16816(acc[mi][ni], ah[mi], bh[j][s], bh[j][s + 2]);
                    mma16816(acc[mi][ni], al[mi], bh[j][s], bh[j][s + 2]);
                    mma16816(acc[mi][ni], ah[mi], bl[j][s], bl[j][s + 2]);
                }
            }
        }
        __syncthreads();
    }

    // epilogue: acc -> +bias -> out
    const int rbase = m0 + wm * 64 + (lane >> 2);
    const int cbase = n0 + wn * 32 + (lane & 3) * 2;
#pragma unroll
    for (int mi = 0; mi < 4; ++mi) {
#pragma unroll
        for (int ni = 0; ni < 4; ++ni) {
            const int rm = rbase + mi * 16;
            const int cn = cbase + ni * 8;
            float2 bv = *(const float2*)(bias + cn);
            float2 o0, o1;
            o0.x = acc[mi][ni][0] + bv.x;
            o0.y = acc[mi][ni][1] + bv.y;
            o1.x = acc[mi][ni][2] + bv.x;
            o1.y = acc[mi][ni][3] + bv.y;
            *(float2*)(out + (size_t)rm * DOUT + cn) = o0;
            *(float2*)(out + (size_t)(rm + 8) * DOUT + cn) = o1;
        }
    }
}

// ---------------- launch ----------------
extern "C" void kernel_launch(void* const* d_in, const int* in_sizes, int n_in,
                              void* d_out, int out_size) {
    const float* x      = (const float*)d_in[0];
    const float* weight = (const float*)d_in[1];
    const float* bias   = (const float*)d_in[2];
    const float* scores = (const float*)d_in[3];
    const float* noise  = (const float*)d_in[4];
    float* out = (float*)d_out;

    // arch probe (no-op under non-accelerated pass; tells us next round which image loaded)
    probe_sm103a_feat_kernel<<<16, 256>>>();
    // 1) split x into bf16 hi/lo
    split_x_kernel<<<(unsigned)((size_t)NROWS * DIN / 4 / 256), 256>>>((const float4*)x);
    // 2) gumbel top-2 mask + masked-weight bf16 hi/lo split
    mask_split_w_kernel<<<(unsigned)((size_t)DOUT * (DIN / 4) / 256), 256>>>(weight, scores, noise);
    // 3) GEMM + bias epilogue
    cudaFuncSetAttribute(gemm_mma_kernel, cudaFuncAttributeMaxDynamicSharedMemorySize, F_SMEM);
    gemm_mma_kernel<<<dim3(NROWS / FTM, DOUT / FTN), 256, F_SMEM>>>(bias, out);
}

// round 15
// speedup vs baseline: 1.0027x; 1.0027x over previous
#include <cuda_runtime.h>
#include <cuda_bf16.h>
#include <cstdint>

// ---------------- problem dims ----------------
#define DIN   4096
#define DOUT  4096
#define NROWS 16384            // 8 * 2048

// Feature probe: tcgen05-capable pass defines __CUDA_ARCH_FEAT_SM103_ALL.
#if defined(__CUDA_ARCH__) && defined(__CUDA_ARCH_FEAT_SM103_ALL)
#define TC_ACTIVE 1
#else
#define TC_ACTIVE 0
#endif

// ---------------- scratch (device globals: no allocation allowed) ----------------
__device__ __nv_bfloat16 g_xhi[(size_t)NROWS * DIN];   // 128MB
__device__ __nv_bfloat16 g_xlo[(size_t)NROWS * DIN];   // 128MB
__device__ __nv_bfloat16 g_whi[(size_t)DOUT * DIN];    // 32MB
__device__ __nv_bfloat16 g_wlo[(size_t)DOUT * DIN];    // 32MB
__device__ unsigned int  g_probe[4096];                // arch-probe sink (never read)

// ---------------- common helpers ----------------
__device__ __forceinline__ uint32_t smem_to_u32(const void* smem_ptr) {
    uint32_t addr;
    asm("{ .reg .u64 tmp; cvta.to.shared.u64 tmp, %1; cvt.u32.u64 %0, tmp; }"
        : "=r"(addr) : "l"(smem_ptr));
    return addr;
}

__device__ __forceinline__ uint32_t swz(uint32_t off) {   // SW128 swizzle
    return off ^ ((off >> 3) & 0x70);
}

__device__ __forceinline__ uint32_t pack2bf(__nv_bfloat16 a, __nv_bfloat16 b) {
    return (uint32_t)__bfloat16_as_ushort(a) | ((uint32_t)__bfloat16_as_ushort(b) << 16);
}

// ================= arch probe: body only under sm_103a feature pass =================
__global__ void probe_sm103a_feat_kernel() {
#if TC_ACTIVE
    unsigned i = blockIdx.x * blockDim.x + threadIdx.x;
    if (i < 4096) g_probe[i] = i * 2654435761u;
#endif
}

// ================= prep kernels =================
__global__ void split_x_kernel(const float4* __restrict__ x) {
    size_t i = (size_t)blockIdx.x * blockDim.x + threadIdx.x;
    if (i >= (size_t)NROWS * DIN / 4) return;
    float4 v = x[i];
    __nv_bfloat16 h0 = __float2bfloat16(v.x);
    __nv_bfloat16 h1 = __float2bfloat16(v.y);
    __nv_bfloat16 h2 = __float2bfloat16(v.z);
    __nv_bfloat16 h3 = __float2bfloat16(v.w);
    __nv_bfloat16 l0 = __float2bfloat16(v.x - __bfloat162float(h0));
    __nv_bfloat16 l1 = __float2bfloat16(v.y - __bfloat162float(h1));
    __nv_bfloat16 l2 = __float2bfloat16(v.z - __bfloat162float(h2));
    __nv_bfloat16 l3 = __float2bfloat16(v.w - __bfloat162float(h3));
    ((uint2*)g_xhi)[i] = make_uint2(pack2bf(h0, h1), pack2bf(h2, h3));
    ((uint2*)g_xlo)[i] = make_uint2(pack2bf(l0, l1), pack2bf(l2, l3));
}

__device__ __forceinline__ float gumbel_of(float u) {
    return -logf(-logf(u + 1e-10f) + 1e-10f);
}

__global__ void mask_split_w_kernel(const float* __restrict__ weight,
                                    const float* __restrict__ scores,
                                    const float* __restrict__ noise) {
    size_t gi = (size_t)blockIdx.x * blockDim.x + threadIdx.x;
    if (gi >= (size_t)DOUT * (DIN / 4)) return;
    float4 s4 = ((const float4*)scores)[gi];
    float4 u4 = ((const float4*)noise)[gi];
    float y[4];
    y[0] = s4.x + gumbel_of(u4.x);
    y[1] = s4.y + gumbel_of(u4.y);
    y[2] = s4.z + gumbel_of(u4.z);
    y[3] = s4.w + gumbel_of(u4.w);
    float mx = fmaxf(fmaxf(y[0], y[1]), fmaxf(y[2], y[3]));
    float e[4];
#pragma unroll
    for (int j = 0; j < 4; ++j) e[j] = expf(y[j] - mx);
    float ssum = ((e[0] + e[1]) + e[2]) + e[3];
    float q[4];
#pragma unroll
    for (int j = 0; j < 4; ++j) q[j] = e[j] / ssum;
    // top-2 (stable: ties -> lower index, matching jax top_k)
    int i0 = 0;
#pragma unroll
    for (int j = 1; j < 4; ++j) if (q[j] > q[i0]) i0 = j;
    int i1 = (i0 == 0) ? 1 : 0;
#pragma unroll
    for (int j = 0; j < 4; ++j) if (j != i0 && q[j] > q[i1]) i1 = j;

    float4 w4 = ((const float4*)weight)[gi];
    float wm[4] = {w4.x, w4.y, w4.z, w4.w};
#pragma unroll
    for (int j = 0; j < 4; ++j) if (j != i0 && j != i1) wm[j] = 0.0f;

    __nv_bfloat16 h[4], l[4];
#pragma unroll
    for (int j = 0; j < 4; ++j) {
        h[j] = __float2bfloat16(wm[j]);
        l[j] = __float2bfloat16(wm[j] - __bfloat162float(h[j]));
    }
    ((uint2*)g_whi)[gi] = make_uint2(pack2bf(h[0], h[1]), pack2bf(h[2], h[3]));
    ((uint2*)g_wlo)[gi] = make_uint2(pack2bf(l[0], l[1]), pack2bf(l[2], l[3]));
}

// =====================================================================
// GEMM: mma.sync.m16n8k16 bf16, 128x128 CTA tile, cp.async double buffer.
// D[m,n] = sum_k A[m,k]*B[n,k], 3-term bf16 hi/lo split, fp32 accum.
// =====================================================================
#define FTM 128
#define FTN 128
#define FKS 64                  // K elems per stage (128B rows, SW128)
#define FNST (DIN / FKS)        // 64
#define F_TILE 16384            // one 128x64 bf16 tile (16KB), swizzled
#define F_STAGE (4 * F_TILE)    // Ahi,Alo,Bhi,Blo = 64KB
#define F_SMEM (2 * F_STAGE)    // 131072

__device__ __forceinline__ void ldmx4(uint32_t* r, uint32_t addr) {
    asm volatile("ldmatrix.sync.aligned.m8n8.x4.shared.b16 {%0,%1,%2,%3}, [%4];"
        : "=r"(r[0]), "=r"(r[1]), "=r"(r[2]), "=r"(r[3]) : "r"(addr));
}

__device__ __forceinline__ void mma16816(float* c, const uint32_t* a, uint32_t b0, uint32_t b1) {
    asm volatile(
        "mma.sync.aligned.m16n8k16.row.col.f32.bf16.bf16.f32 "
        "{%0,%1,%2,%3}, {%4,%5,%6,%7}, {%8,%9}, {%0,%1,%2,%3};"
        : "+f"(c[0]), "+f"(c[1]), "+f"(c[2]), "+f"(c[3])
        : "r"(a[0]), "r"(a[1]), "r"(a[2]), "r"(a[3]), "r"(b0), "r"(b1));
}

__device__ __forceinline__ void cp16(uint32_t dst, const void* src) {
    asm volatile("cp.async.cg.shared.global [%0], [%1], 16;" :: "r"(dst), "l"(src));
}
#define CP_COMMIT() asm volatile("cp.async.commit_group;" ::: "memory")
#define CP_WAIT0()  asm volatile("cp.async.wait_group 0;" ::: "memory")

// issue one full stage: 4 tiles x 1024 chunks of 16B; 256 threads x 4 chunks/tile
__device__ __forceinline__ void issue_stage(uint32_t sbase, int tid, int m0, int n0, int k0) {
#pragma unroll
    for (int i = 0; i < 4; ++i) {
        int ch = tid + i * 256;               // 0..1023
        int row = ch >> 3, col = ch & 7;      // row 0..127, col 0..7 (16B chunks)
        uint32_t sw = swz((uint32_t)((row << 7) + (col << 4)));
        size_t ax = (size_t)(m0 + row) * DIN + k0 + (col << 3);
        size_t bx = (size_t)(n0 + row) * DIN + k0 + (col << 3);
        cp16(sbase + 0 * F_TILE + sw, g_xhi + ax);
        cp16(sbase + 1 * F_TILE + sw, g_xlo + ax);
        cp16(sbase + 2 * F_TILE + sw, g_whi + bx);
        cp16(sbase + 3 * F_TILE + sw, g_wlo + bx);
    }
}

__global__ __launch_bounds__(256, 1)
void gemm_mma_kernel(const float* __restrict__ bias, float* __restrict__ out) {
    extern __shared__ __align__(128) char fsmem[];
    const uint32_t smem_u = smem_to_u32(fsmem);
    const int tid = threadIdx.x;
    const int wid = tid >> 5;
    const int lane = tid & 31;
    const int wm = wid >> 2;          // 0..1 -> 64-row slab (M)
    const int wn = wid & 3;           // 0..3 -> 32-col slab (N)
    const int m0 = blockIdx.x * FTM;
    const int n0 = blockIdx.y * FTN;

    issue_stage(smem_u, tid, m0, n0, 0);
    CP_COMMIT();

    float acc[4][4][4];
#pragma unroll
    for (int a = 0; a < 4; ++a)
#pragma unroll
        for (int b = 0; b < 4; ++b)
#pragma unroll
            for (int c = 0; c < 4; ++c) acc[a][b][c] = 0.0f;

    const uint32_t a_row = (uint32_t)(wm * 64 + (lane & 15));
    const uint32_t b_row = (uint32_t)(wn * 32 + (lane & 15));
    const uint32_t kqual = ((uint32_t)(lane >> 4)) << 4;   // byte offset of k-half

    for (int k = 0; k < FNST; ++k) {
        CP_WAIT0();
        __syncthreads();
        if (k + 1 < FNST) {
            issue_stage(smem_u + (uint32_t)(((k + 1) & 1) * F_STAGE), tid, m0, n0, (k + 1) * FKS);
            CP_COMMIT();
        }
        const uint32_t cur = smem_u + (uint32_t)((k & 1) * F_STAGE);
#pragma unroll
        for (int ks = 0; ks < 4; ++ks) {
            uint32_t ah[4][4], al[4][4], bh[2][4], bl[2][4];
#pragma unroll
            for (int mi = 0; mi < 4; ++mi) {
                uint32_t sa = swz(((a_row + mi * 16) << 7) + (ks << 5) + kqual);
                ldmx4(ah[mi], cur + 0 * F_TILE + sa);
                ldmx4(al[mi], cur + 1 * F_TILE + sa);
            }
#pragma unroll
            for (int nj = 0; nj < 2; ++nj) {
                uint32_t sb = swz(((b_row + nj * 16) << 7) + (ks << 5) + kqual);
                ldmx4(bh[nj], cur + 2 * F_TILE + sb);
                ldmx4(bl[nj], cur + 3 * F_TILE + sb);
            }
#pragma unroll
            for (int mi = 0; mi < 4; ++mi) {
#pragma unroll
                for (int ni = 0; ni < 4; ++ni) {
                    const int j = ni >> 1, s = ni & 1;
                    mma16816(acc[mi][ni], ah[mi], bh[j][s], bh[j][s + 2]);
                    mma16816(acc[mi][ni], al[mi], bh[j][s], bh[j][s + 2]);
                    mma16816(acc[mi][ni], ah[mi], bl[j][s], bl[j][s + 2]);
                }
            }
        }
        __syncthreads();
    }

    // epilogue: acc -> +bias -> out
    const int rbase = m0 + wm * 64 + (lane >> 2);
    const int cbase = n0 + wn * 32 + (lane & 3) * 2;
#pragma unroll
    for (int mi = 0; mi < 4; ++mi) {
#pragma unroll
        for (int ni = 0; ni < 4; ++ni) {
            const int rm = rbase + mi * 16;
            const int cn = cbase + ni * 8;
            float2 bv = *(const float2*)(bias + cn);
            float2 o0, o1;
            o0.x = acc[mi][ni][0] + bv.x;
            o0.y = acc[mi][ni][1] + bv.y;
            o1.x = acc[mi][ni][2] + bv.x;
            o1.y = acc[mi][ni][3] + bv.y;
            *(float2*)(out + (size_t)rm * DOUT + cn) = o0;
            *(float2*)(out + (size_t)(rm + 8) * DOUT + cn) = o1;
        }
    }
}

// ---------------- launch ----------------
extern "C" void kernel_launch(void* const* d_in, const int* in_sizes, int n_in,
                              void* d_out, int out_size) {
    const float* x      = (const float*)d_in[0];
    const float* weight = (const float*)d_in[1];
    const float* bias   = (const float*)d_in[2];
    const float* scores = (const float*)d_in[3];
    const float* noise  = (const float*)d_in[4];
    float* out = (float*)d_out;

    // arch probe (no-op under non-accelerated pass; tells us next round which image loaded)
    probe_sm103a_feat_kernel<<<16, 256>>>();
    // 1) split x into bf16 hi/lo
    split_x_kernel<<<(unsigned)((size_t)NROWS * DIN / 4 / 256), 256>>>((const float4*)x);
    // 2) gumbel top-2 mask + masked-weight bf16 hi/lo split
    mask_split_w_kernel<<<(unsigned)((size_t)DOUT * (DIN / 4) / 256), 256>>>(weight, scores, noise);
    // 3) GEMM + bias epilogue
    cudaFuncSetAttribute(gemm_mma_kernel, cudaFuncAttributeMaxDynamicSharedMemorySize, F_SMEM);
    gemm_mma_kernel<<<dim3(NROWS / FTM, DOUT / FTN), 256, F_SMEM>>>(bias, out);
}